// round 7
// baseline (speedup 1.0000x reference)
#include <cuda_runtime.h>
#include <math.h>

#define Bsz 4
#define Nn 1024
#define Dd 1024
#define Hh 8
#define HD 128
#define ROWS (Bsz * Nn)          // 4096
#define MAXNBR 192

// ---------------- scratch (static device globals; no allocation) ------------
__device__ float g_normed[ROWS * Dd];     // 16 MB  LN1 output
__device__ float g_h[ROWS * Dd];          // 16 MB  x + attn (residual stream)
__device__ float g_normed2[ROWS * Dd];    // 16 MB  LN2 output
__device__ float g_mlp1[ROWS * 4 * Dd];   // 64 MB  gelu(normed2 @ W1 + b1)
__device__ int   g_nbr_idx[ROWS * MAXNBR];
__device__ int   g_nbr_cnt[ROWS];

// ---------------- LayerNorm: one block per row ------------------------------
__global__ void ln_kernel(const float* __restrict__ in,
                          const float* __restrict__ gamma,
                          const float* __restrict__ beta,
                          float* __restrict__ out) {
    int row = blockIdx.x;
    int tid = threadIdx.x;
    const float* p = in + (size_t)row * Dd;
    float s = 0.f, s2 = 0.f;
    for (int i = tid; i < Dd; i += 256) {
        float v = p[i];
        s += v; s2 += v * v;
    }
    __shared__ float rs[256], rs2[256];
    rs[tid] = s; rs2[tid] = s2;
    __syncthreads();
    for (int o = 128; o; o >>= 1) {
        if (tid < o) { rs[tid] += rs[tid + o]; rs2[tid] += rs2[tid + o]; }
        __syncthreads();
    }
    float mu = rs[0] * (1.f / Dd);
    float var = rs2[0] * (1.f / Dd) - mu * mu;
    float inv = rsqrtf(var + 1e-5f);
    float* q = out + (size_t)row * Dd;
    for (int i = tid; i < Dd; i += 256)
        q[i] = (p[i] - mu) * inv * gamma[i] + beta[i];
}

// ---------------- neighbor-list build: one block per (b,q) row --------------
__global__ void build_nbr_kernel(const int* __restrict__ adj) {
    int row = blockIdx.x;                 // b*N + q
    __shared__ int cnt;
    if (threadIdx.x == 0) cnt = 0;
    __syncthreads();
    const int* arow = adj + (size_t)row * Nn;
    for (int k = threadIdx.x; k < Nn; k += 256) {
        if (arow[k] > 0) {
            int pos = atomicAdd(&cnt, 1);
            if (pos < MAXNBR) g_nbr_idx[row * MAXNBR + pos] = k;
        }
    }
    __syncthreads();
    if (threadIdx.x == 0) g_nbr_cnt[row] = min(cnt, MAXNBR);
}

// ---------------- sparse attention + residual: one block per (b,q) ----------
// 8 warps = 8 heads. Writes g_h = x + attn_out.
__global__ void attn_kernel(const float* __restrict__ x,
                            const float* __restrict__ stoich,
                            const float* __restrict__ gW,
                            const float* __restrict__ gb) {
    int row = blockIdx.x;
    int b = row >> 10;
    int tid = threadIdx.x;

    __shared__ float qrow[Dd];
    __shared__ float gate[MAXNBR];
    __shared__ int   nbr_s[MAXNBR];
    __shared__ float sc[Hh][MAXNBR];

    int cnt = g_nbr_cnt[row];

    // load q row (LN1 output) into smem: 256 float4
    ((float4*)qrow)[tid] = ((const float4*)(g_normed + (size_t)row * Dd))[tid];

    float st = stoich[row];
    for (int j = tid; j < cnt; j += 256) {
        int k = g_nbr_idx[row * MAXNBR + j];
        nbr_s[j] = k;
        gate[j] = 1.f / (1.f + expf(-(st * gW[k] + gb[k])));
    }
    __syncthreads();

    int wid = tid >> 5, lane = tid & 31;
    const float* base = g_normed + (size_t)b * Nn * Dd;
    float4 qv = ((const float4*)qrow)[wid * 32 + lane];

    const float scale = 0.08838834764831845f;  // 1/sqrt(128)
    float m = -INFINITY;
    for (int j = 0; j < cnt; j++) {
        int k = nbr_s[j];
        float4 kv = ((const float4*)(base + (size_t)k * Dd + wid * HD))[lane];
        float d = qv.x * kv.x + qv.y * kv.y + qv.z * kv.z + qv.w * kv.w;
#pragma unroll
        for (int o = 16; o; o >>= 1) d += __shfl_xor_sync(0xffffffffu, d, o);
        float s = d * scale * gate[j];
        if (lane == 0) sc[wid][j] = s;
        m = fmaxf(m, s);
    }
    __syncwarp();

    float Z = 0.f;
    for (int j = lane; j < cnt; j += 32) Z += expf(sc[wid][j] - m);
#pragma unroll
    for (int o = 16; o; o >>= 1) Z += __shfl_xor_sync(0xffffffffu, Z, o);
    float invZ = 1.f / Z;

    float4 acc = make_float4(0.f, 0.f, 0.f, 0.f);
    for (int j = 0; j < cnt; j++) {
        float p = expf(sc[wid][j] - m) * invZ;
        int k = nbr_s[j];
        float4 kv = ((const float4*)(base + (size_t)k * Dd + wid * HD))[lane];
        acc.x += p * kv.x; acc.y += p * kv.y; acc.z += p * kv.z; acc.w += p * kv.w;
    }

    size_t off = (size_t)row * Dd + wid * HD + lane * 4;
    float4 xv = *(const float4*)(x + off);
    float4 o4 = make_float4(xv.x + acc.x, xv.y + acc.y, xv.z + acc.z, xv.w + acc.w);
    *(float4*)(g_h + off) = o4;
}

// ---------------- SGEMM 128x128x16, 256 threads, 8x8 per thread -------------
__device__ __forceinline__ float gelu_exact(float v) {
    return 0.5f * v * (1.f + erff(v * 0.70710678118654752f));
}

template <int ACT>  // 1: gelu epilogue; 0: +residual epilogue
__global__ void sgemm_kernel(const float* __restrict__ A,
                             const float* __restrict__ B,
                             const float* __restrict__ bias,
                             const float* __restrict__ res,
                             float* __restrict__ C,
                             int M, int N, int K) {
    const int BK = 16, TM = 8, TN = 8;
    __shared__ float As[BK][128];
    __shared__ float Bs[BK][128];

    int tid = threadIdx.x;
    int br = blockIdx.y, bc = blockIdx.x;

    int aRow  = tid >> 2;   // 0..63
    int aCol4 = tid & 3;    // float4 slot in 16-wide K tile
    int bRow  = tid >> 5;   // 0..7
    int bCol4 = tid & 31;   // float4 slot in 128-wide N tile

    int tr = tid >> 4, tc = tid & 15;
    float acc[TM][TN] = {};

    for (int k0 = 0; k0 < K; k0 += BK) {
#pragma unroll
        for (int t = 0; t < 2; t++) {
            int r = aRow + t * 64;
            float4 v = *(const float4*)&A[(size_t)(br * 128 + r) * K + k0 + aCol4 * 4];
            As[aCol4 * 4 + 0][r] = v.x;
            As[aCol4 * 4 + 1][r] = v.y;
            As[aCol4 * 4 + 2][r] = v.z;
            As[aCol4 * 4 + 3][r] = v.w;
        }
#pragma unroll
        for (int t = 0; t < 2; t++) {
            int r = bRow + t * 8;
            float4 v = *(const float4*)&B[(size_t)(k0 + r) * N + bc * 128 + bCol4 * 4];
            *(float4*)&Bs[r][bCol4 * 4] = v;
        }
        __syncthreads();

#pragma unroll
        for (int kk = 0; kk < BK; kk++) {
            float ra[TM], rb[TN];
#pragma unroll
            for (int i = 0; i < TM; i++) ra[i] = As[kk][tr * TM + i];
#pragma unroll
            for (int j = 0; j < TN; j++) rb[j] = Bs[kk][tc * TN + j];
#pragma unroll
            for (int i = 0; i < TM; i++)
#pragma unroll
                for (int j = 0; j < TN; j++) acc[i][j] += ra[i] * rb[j];
        }
        __syncthreads();
    }

#pragma unroll
    for (int i = 0; i < TM; i++) {
        int row = br * 128 + tr * TM + i;
#pragma unroll
        for (int j = 0; j < TN; j++) {
            int col = bc * 128 + tc * TN + j;
            float v = acc[i][j] + bias[col];
            if (ACT) {
                v = gelu_exact(v);
            } else {
                v += res[(size_t)row * N + col];
            }
            C[(size_t)row * N + col] = v;
        }
    }
}

// ---------------- launch -----------------------------------------------------
extern "C" void kernel_launch(void* const* d_in, const int* in_sizes, int n_in,
                              void* d_out, int out_size) {
    const float* x      = (const float*)d_in[0];
    const int*   adj    = (const int*)d_in[1];
    const float* stoich = (const float*)d_in[2];
    const float* ln1_g  = (const float*)d_in[3];
    const float* ln1_b  = (const float*)d_in[4];
    const float* ln2_g  = (const float*)d_in[5];
    const float* ln2_b  = (const float*)d_in[6];
    const float* W1     = (const float*)d_in[7];
    const float* b1     = (const float*)d_in[8];
    const float* W2     = (const float*)d_in[9];
    const float* b2     = (const float*)d_in[10];
    const float* gW     = (const float*)d_in[11];
    const float* gb     = (const float*)d_in[12];
    float* out = (float*)d_out;

    float *normed, *hbuf, *normed2, *mlp1;
    cudaGetSymbolAddress((void**)&normed,  g_normed);
    cudaGetSymbolAddress((void**)&hbuf,    g_h);
    cudaGetSymbolAddress((void**)&normed2, g_normed2);
    cudaGetSymbolAddress((void**)&mlp1,    g_mlp1);

    // 1. LN1
    ln_kernel<<<ROWS, 256>>>(x, ln1_g, ln1_b, normed);
    // 2. neighbor lists
    build_nbr_kernel<<<ROWS, 256>>>(adj);
    // 3. sparse attention + residual -> g_h
    attn_kernel<<<ROWS, 256>>>(x, stoich, gW, gb);
    // 4. LN2
    ln_kernel<<<ROWS, 256>>>(hbuf, ln2_g, ln2_b, normed2);
    // 5. mlp1 = gelu(normed2 @ W1 + b1)   [4096 x 4096]
    {
        dim3 grid(4 * Dd / 128, ROWS / 128);
        sgemm_kernel<1><<<grid, 256>>>(normed2, W1, b1, nullptr, mlp1,
                                       ROWS, 4 * Dd, Dd);
    }
    // 6. out = mlp1 @ W2 + b2 + g_h      [4096 x 1024]
    {
        dim3 grid(Dd / 128, ROWS / 128);
        sgemm_kernel<0><<<grid, 256>>>(mlp1, W2, b2, hbuf, out,
                                       ROWS, Dd, 4 * Dd);
    }
}

// round 10
// speedup vs baseline: 2.8573x; 2.8573x over previous
#include <cuda_runtime.h>
#include <math.h>

#define Bsz 4
#define Nn 1024
#define Dd 1024
#define Hh 8
#define HD 128
#define ROWS (Bsz * Nn)          // 4096
#define MAXNBR 192

// ---------------- scratch (static device globals; no allocation) ------------
__device__ float g_normed[ROWS * Dd];     // 16 MB  LN1 output
__device__ float g_h[ROWS * Dd];          // 16 MB  x + attn (residual stream)
__device__ float g_normed2[ROWS * Dd];    // 16 MB  LN2 output
__device__ float g_mlp1[ROWS * 4 * Dd];   // 64 MB  gelu(normed2 @ W1 + b1)
__device__ int   g_nbr_idx[ROWS * MAXNBR];
__device__ int   g_nbr_cnt[ROWS];

// ---------------- LayerNorm: one block per row ------------------------------
__global__ void ln_kernel(const float* __restrict__ in,
                          const float* __restrict__ gamma,
                          const float* __restrict__ beta,
                          float* __restrict__ out) {
    int row = blockIdx.x;
    int tid = threadIdx.x;
    const float* p = in + (size_t)row * Dd;
    float s = 0.f, s2 = 0.f;
    for (int i = tid; i < Dd; i += 256) {
        float v = p[i];
        s += v; s2 += v * v;
    }
    __shared__ float rs[256], rs2[256];
    rs[tid] = s; rs2[tid] = s2;
    __syncthreads();
    for (int o = 128; o; o >>= 1) {
        if (tid < o) { rs[tid] += rs[tid + o]; rs2[tid] += rs2[tid + o]; }
        __syncthreads();
    }
    float mu = rs[0] * (1.f / Dd);
    float var = rs2[0] * (1.f / Dd) - mu * mu;
    float inv = rsqrtf(var + 1e-5f);
    float* q = out + (size_t)row * Dd;
    for (int i = tid; i < Dd; i += 256)
        q[i] = (p[i] - mu) * inv * gamma[i] + beta[i];
}

// ---------------- neighbor-list build: one block per (b,q) row --------------
__global__ void build_nbr_kernel(const int* __restrict__ adj) {
    int row = blockIdx.x;                 // b*N + q
    __shared__ int cnt;
    if (threadIdx.x == 0) cnt = 0;
    __syncthreads();
    const int* arow = adj + (size_t)row * Nn;
    for (int k = threadIdx.x; k < Nn; k += 256) {
        if (arow[k] > 0) {
            int pos = atomicAdd(&cnt, 1);
            if (pos < MAXNBR) g_nbr_idx[row * MAXNBR + pos] = k;
        }
    }
    __syncthreads();
    if (threadIdx.x == 0) g_nbr_cnt[row] = min(cnt, MAXNBR);
}

// ---------------- sparse attention + residual: one block per (b,q) ----------
__global__ void attn_kernel(const float* __restrict__ x,
                            const float* __restrict__ stoich,
                            const float* __restrict__ gW,
                            const float* __restrict__ gb) {
    int row = blockIdx.x;
    int b = row >> 10;
    int tid = threadIdx.x;

    __shared__ float qrow[Dd];
    __shared__ float gate[MAXNBR];
    __shared__ int   nbr_s[MAXNBR];
    __shared__ float sc[Hh][MAXNBR];

    int cnt = g_nbr_cnt[row];

    ((float4*)qrow)[tid] = ((const float4*)(g_normed + (size_t)row * Dd))[tid];

    float st = stoich[row];
    for (int j = tid; j < cnt; j += 256) {
        int k = g_nbr_idx[row * MAXNBR + j];
        nbr_s[j] = k;
        gate[j] = 1.f / (1.f + expf(-(st * gW[k] + gb[k])));
    }
    __syncthreads();

    int wid = tid >> 5, lane = tid & 31;
    const float* base = g_normed + (size_t)b * Nn * Dd;
    float4 qv = ((const float4*)qrow)[wid * 32 + lane];

    const float scale = 0.08838834764831845f;  // 1/sqrt(128)
    float m = -INFINITY;
    for (int j = 0; j < cnt; j++) {
        int k = nbr_s[j];
        float4 kv = ((const float4*)(base + (size_t)k * Dd + wid * HD))[lane];
        float d = qv.x * kv.x + qv.y * kv.y + qv.z * kv.z + qv.w * kv.w;
#pragma unroll
        for (int o = 16; o; o >>= 1) d += __shfl_xor_sync(0xffffffffu, d, o);
        float s = d * scale * gate[j];
        if (lane == 0) sc[wid][j] = s;
        m = fmaxf(m, s);
    }
    __syncwarp();

    float Z = 0.f;
    for (int j = lane; j < cnt; j += 32) Z += expf(sc[wid][j] - m);
#pragma unroll
    for (int o = 16; o; o >>= 1) Z += __shfl_xor_sync(0xffffffffu, Z, o);
    float invZ = 1.f / Z;

    float4 acc = make_float4(0.f, 0.f, 0.f, 0.f);
    for (int j = 0; j < cnt; j++) {
        float p = expf(sc[wid][j] - m) * invZ;
        int k = nbr_s[j];
        float4 kv = ((const float4*)(base + (size_t)k * Dd + wid * HD))[lane];
        acc.x += p * kv.x; acc.y += p * kv.y; acc.z += p * kv.z; acc.w += p * kv.w;
    }

    size_t off = (size_t)row * Dd + wid * HD + lane * 4;
    float4 xv = *(const float4*)(x + off);
    float4 o4 = make_float4(xv.x + acc.x, xv.y + acc.y, xv.z + acc.z, xv.w + acc.w);
    *(float4*)(g_h + off) = o4;
}

// ---------------- TF32 tensor-core GEMM 128x128x32 ---------------------------
__device__ __forceinline__ float gelu_exact(float v) {
    return 0.5f * v * (1.f + erff(v * 0.70710678118654752f));
}

__device__ __forceinline__ unsigned f2tf32(float f) {
    unsigned u;
    asm("cvt.rna.tf32.f32 %0, %1;" : "=r"(u) : "f"(f));
    return u;
}

__device__ __forceinline__ void mma_tf32(float* c, const unsigned* a, const unsigned* b) {
    asm volatile(
        "mma.sync.aligned.m16n8k8.row.col.f32.tf32.tf32.f32 "
        "{%0,%1,%2,%3}, {%4,%5,%6,%7}, {%8,%9}, {%0,%1,%2,%3};"
        : "+f"(c[0]), "+f"(c[1]), "+f"(c[2]), "+f"(c[3])
        : "r"(a[0]), "r"(a[1]), "r"(a[2]), "r"(a[3]), "r"(b[0]), "r"(b[1]));
}

// Block 128x128, BK=32, 256 threads. 8 warps in 2(m) x 4(n); warp tile 64x32.
template <int ACT>  // 1: gelu epilogue; 0: +residual epilogue
__global__ void __launch_bounds__(256)
tgemm_kernel(const float* __restrict__ A,
             const float* __restrict__ B,
             const float* __restrict__ bias,
             const float* __restrict__ res,
             float* __restrict__ C,
             int M, int N, int K) {
    __shared__ unsigned As[128][36];   // [m][k], pad 36: frag bank = 4g+t (CF)
    __shared__ unsigned Bs[32][136];   // [k][n], pad 136: frag bank = 8t+g (CF)

    int tid = threadIdx.x;
    int brow = blockIdx.y, bcol = blockIdx.x;
    int w = tid >> 5, lane = tid & 31;
    int wm = w & 1, wn = w >> 1;          // 2 x 4 warps
    int g = lane >> 2, t = lane & 3;

    // global-load assignments (4 float4 each for A and B tiles)
    int ar = tid >> 3;            // 0..31 (+32*i)
    int ac = (tid & 7) * 4;       // k offset within tile
    int br = tid >> 5;            // 0..7  (+8*i)
    int bc = (tid & 31) * 4;      // n offset within tile

    const float* Ap = A + (size_t)(brow * 128 + ar) * K + ac;
    const float* Bp = B + (size_t)br * N + bcol * 128 + bc;

    float acc[4][4][4] = {};
    float4 pa[4], pb[4];

#pragma unroll
    for (int i = 0; i < 4; i++) {
        pa[i] = *(const float4*)(Ap + (size_t)(i * 32) * K);
        pb[i] = *(const float4*)(Bp + (size_t)(i * 8) * N);
    }

    for (int k0 = 0; k0 < K; k0 += 32) {
#pragma unroll
        for (int i = 0; i < 4; i++) {
            unsigned* da = &As[ar + 32 * i][ac];
            da[0] = f2tf32(pa[i].x); da[1] = f2tf32(pa[i].y);
            da[2] = f2tf32(pa[i].z); da[3] = f2tf32(pa[i].w);
            unsigned* db = &Bs[br + 8 * i][bc];
            db[0] = f2tf32(pb[i].x); db[1] = f2tf32(pb[i].y);
            db[2] = f2tf32(pb[i].z); db[3] = f2tf32(pb[i].w);
        }
        __syncthreads();

        if (k0 + 32 < K) {
#pragma unroll
            for (int i = 0; i < 4; i++) {
                pa[i] = *(const float4*)(Ap + (size_t)(i * 32) * K + k0 + 32);
                pb[i] = *(const float4*)(Bp + (size_t)(k0 + 32 + i * 8) * N);
            }
        }

#pragma unroll
        for (int ks = 0; ks < 4; ks++) {
            int kk = ks * 8 + t;
            unsigned af[4][4], bf[4][2];
#pragma unroll
            for (int mi = 0; mi < 4; mi++) {
                int r = wm * 64 + mi * 16 + g;
                af[mi][0] = As[r][kk];
                af[mi][1] = As[r + 8][kk];
                af[mi][2] = As[r][kk + 4];
                af[mi][3] = As[r + 8][kk + 4];
            }
#pragma unroll
            for (int ni = 0; ni < 4; ni++) {
                int n = wn * 32 + ni * 8 + g;
                bf[ni][0] = Bs[kk][n];
                bf[ni][1] = Bs[kk + 4][n];
            }
#pragma unroll
            for (int mi = 0; mi < 4; mi++)
#pragma unroll
                for (int ni = 0; ni < 4; ni++)
                    mma_tf32(acc[mi][ni], af[mi], bf[ni]);
        }
        __syncthreads();
    }

    // epilogue: c0,c1 at (row0, col..col+1); c2,c3 at (row0+8, col..col+1)
#pragma unroll
    for (int mi = 0; mi < 4; mi++) {
        int row0 = brow * 128 + wm * 64 + mi * 16 + g;
#pragma unroll
        for (int ni = 0; ni < 4; ni++) {
            int col = bcol * 128 + wn * 32 + ni * 8 + 2 * t;
            float b0 = bias[col], b1 = bias[col + 1];
            float v0 = acc[mi][ni][0] + b0;
            float v1 = acc[mi][ni][1] + b1;
            float v2 = acc[mi][ni][2] + b0;
            float v3 = acc[mi][ni][3] + b1;
            if (ACT) {
                v0 = gelu_exact(v0); v1 = gelu_exact(v1);
                v2 = gelu_exact(v2); v3 = gelu_exact(v3);
            } else {
                const float* r0 = res + (size_t)row0 * N + col;
                const float* r1 = res + (size_t)(row0 + 8) * N + col;
                v0 += r0[0]; v1 += r0[1];
                v2 += r1[0]; v3 += r1[1];
            }
            float2* o0 = (float2*)(C + (size_t)row0 * N + col);
            float2* o1 = (float2*)(C + (size_t)(row0 + 8) * N + col);
            *o0 = make_float2(v0, v1);
            *o1 = make_float2(v2, v3);
        }
    }
}

// ---------------- launch -----------------------------------------------------
extern "C" void kernel_launch(void* const* d_in, const int* in_sizes, int n_in,
                              void* d_out, int out_size) {
    const float* x      = (const float*)d_in[0];
    const int*   adj    = (const int*)d_in[1];
    const float* stoich = (const float*)d_in[2];
    const float* ln1_g  = (const float*)d_in[3];
    const float* ln1_b  = (const float*)d_in[4];
    const float* ln2_g  = (const float*)d_in[5];
    const float* ln2_b  = (const float*)d_in[6];
    const float* W1     = (const float*)d_in[7];
    const float* b1     = (const float*)d_in[8];
    const float* W2     = (const float*)d_in[9];
    const float* b2     = (const float*)d_in[10];
    const float* gW     = (const float*)d_in[11];
    const float* gb     = (const float*)d_in[12];
    float* out = (float*)d_out;

    float *normed, *hbuf, *normed2, *mlp1;
    cudaGetSymbolAddress((void**)&normed,  g_normed);
    cudaGetSymbolAddress((void**)&hbuf,    g_h);
    cudaGetSymbolAddress((void**)&normed2, g_normed2);
    cudaGetSymbolAddress((void**)&mlp1,    g_mlp1);

    // 1. LN1
    ln_kernel<<<ROWS, 256>>>(x, ln1_g, ln1_b, normed);
    // 2. neighbor lists
    build_nbr_kernel<<<ROWS, 256>>>(adj);
    // 3. sparse attention + residual -> g_h
    attn_kernel<<<ROWS, 256>>>(x, stoich, gW, gb);
    // 4. LN2
    ln_kernel<<<ROWS, 256>>>(hbuf, ln2_g, ln2_b, normed2);
    // 5. mlp1 = gelu(normed2 @ W1 + b1)   [4096 x 4096] K=1024
    {
        dim3 grid(4 * Dd / 128, ROWS / 128);
        tgemm_kernel<1><<<grid, 256>>>(normed2, W1, b1, nullptr, mlp1,
                                       ROWS, 4 * Dd, Dd);
    }
    // 6. out = mlp1 @ W2 + b2 + g_h      [4096 x 1024] K=4096
    {
        dim3 grid(Dd / 128, ROWS / 128);
        tgemm_kernel<0><<<grid, 256>>>(mlp1, W2, b2, hbuf, out,
                                       ROWS, Dd, 4 * Dd);
    }
}

// round 14
// speedup vs baseline: 2.8742x; 1.0059x over previous
#include <cuda_runtime.h>
#include <math.h>

#define Bsz 4
#define Nn 1024
#define Dd 1024
#define Hh 8
#define HD 128
#define ROWS (Bsz * Nn)          // 4096
#define MAXNBR 192

// ---------------- scratch (static device globals; no allocation) ------------
__device__ float g_normed[ROWS * Dd];     // 16 MB  LN1 output
__device__ float g_h[ROWS * Dd];          // 16 MB  x + attn (residual stream)
__device__ float g_normed2[ROWS * Dd];    // 16 MB  LN2 output
__device__ float g_mlp1[ROWS * 4 * Dd];   // 64 MB  gelu(normed2 @ W1 + b1)
__device__ int   g_nbr_idx[ROWS * MAXNBR];
__device__ int   g_nbr_cnt[ROWS];

// ---------------- LayerNorm: one block per row ------------------------------
__global__ void ln_kernel(const float* __restrict__ in,
                          const float* __restrict__ gamma,
                          const float* __restrict__ beta,
                          float* __restrict__ out) {
    int row = blockIdx.x;
    int tid = threadIdx.x;
    const float* p = in + (size_t)row * Dd;
    float s = 0.f, s2 = 0.f;
    for (int i = tid; i < Dd; i += 256) {
        float v = p[i];
        s += v; s2 += v * v;
    }
    __shared__ float rs[256], rs2[256];
    rs[tid] = s; rs2[tid] = s2;
    __syncthreads();
    for (int o = 128; o; o >>= 1) {
        if (tid < o) { rs[tid] += rs[tid + o]; rs2[tid] += rs2[tid + o]; }
        __syncthreads();
    }
    float mu = rs[0] * (1.f / Dd);
    float var = rs2[0] * (1.f / Dd) - mu * mu;
    float inv = rsqrtf(var + 1e-5f);
    float* q = out + (size_t)row * Dd;
    for (int i = tid; i < Dd; i += 256)
        q[i] = (p[i] - mu) * inv * gamma[i] + beta[i];
}

// ---------------- neighbor-list build: one block per (b,q) row --------------
__global__ void build_nbr_kernel(const int* __restrict__ adj) {
    int row = blockIdx.x;                 // b*N + q
    __shared__ int cnt;
    if (threadIdx.x == 0) cnt = 0;
    __syncthreads();
    const int* arow = adj + (size_t)row * Nn;
    for (int k = threadIdx.x; k < Nn; k += 256) {
        if (arow[k] > 0) {
            int pos = atomicAdd(&cnt, 1);
            if (pos < MAXNBR) g_nbr_idx[row * MAXNBR + pos] = k;
        }
    }
    __syncthreads();
    if (threadIdx.x == 0) g_nbr_cnt[row] = min(cnt, MAXNBR);
}

// ---------------- sparse attention (online softmax, single K pass) ----------
// One block per (b,q); 8 warps = 8 heads. Writes g_h = x + attn_out.
__global__ void attn_kernel(const float* __restrict__ x,
                            const float* __restrict__ stoich,
                            const float* __restrict__ gW,
                            const float* __restrict__ gb) {
    int row = blockIdx.x;
    int b = row >> 10;
    int tid = threadIdx.x;

    __shared__ float qrow[Dd];
    __shared__ float gate[MAXNBR];
    __shared__ int   nbr_s[MAXNBR];

    int cnt = g_nbr_cnt[row];

    ((float4*)qrow)[tid] = ((const float4*)(g_normed + (size_t)row * Dd))[tid];

    float st = stoich[row];
    for (int j = tid; j < cnt; j += 256) {
        int k = g_nbr_idx[row * MAXNBR + j];
        nbr_s[j] = k;
        gate[j] = 1.f / (1.f + expf(-(st * gW[k] + gb[k])));
    }
    __syncthreads();

    int wid = tid >> 5, lane = tid & 31;
    const float* base = g_normed + (size_t)b * Nn * Dd;
    float4 qv = ((const float4*)qrow)[wid * 32 + lane];

    const float scale = 0.08838834764831845f;  // 1/sqrt(128)
    float m = -INFINITY, Z = 0.f;
    float4 acc = make_float4(0.f, 0.f, 0.f, 0.f);

    for (int j = 0; j < cnt; j++) {
        int k = nbr_s[j];
        float4 kv = ((const float4*)(base + (size_t)k * Dd + wid * HD))[lane];
        float d = qv.x * kv.x + qv.y * kv.y + qv.z * kv.z + qv.w * kv.w;
#pragma unroll
        for (int o = 16; o; o >>= 1) d += __shfl_xor_sync(0xffffffffu, d, o);
        float s = d * scale * gate[j];
        float mNew = fmaxf(m, s);
        float corr = expf(m - mNew);     // 1.0 when m unchanged (and 0 on first iter: exp(-inf)=0)
        float p = expf(s - mNew);
        Z = Z * corr + p;
        acc.x = acc.x * corr + p * kv.x;
        acc.y = acc.y * corr + p * kv.y;
        acc.z = acc.z * corr + p * kv.z;
        acc.w = acc.w * corr + p * kv.w;
        m = mNew;
    }
    float invZ = 1.f / Z;

    size_t off = (size_t)row * Dd + wid * HD + lane * 4;
    float4 xv = *(const float4*)(x + off);
    float4 o4 = make_float4(xv.x + acc.x * invZ, xv.y + acc.y * invZ,
                            xv.z + acc.z * invZ, xv.w + acc.w * invZ);
    *(float4*)(g_h + off) = o4;
}

// ---------------- TF32 tensor-core GEMM 128x128x32, double-buffered ----------
__device__ __forceinline__ float gelu_exact(float v) {
    return 0.5f * v * (1.f + erff(v * 0.70710678118654752f));
}

__device__ __forceinline__ unsigned f2tf32(float f) {
    unsigned u;
    asm("cvt.rna.tf32.f32 %0, %1;" : "=r"(u) : "f"(f));
    return u;
}

__device__ __forceinline__ void mma_tf32(float* c, const unsigned* a, const unsigned* b) {
    asm volatile(
        "mma.sync.aligned.m16n8k8.row.col.f32.tf32.tf32.f32 "
        "{%0,%1,%2,%3}, {%4,%5,%6,%7}, {%8,%9}, {%0,%1,%2,%3};"
        : "+f"(c[0]), "+f"(c[1]), "+f"(c[2]), "+f"(c[3])
        : "r"(a[0]), "r"(a[1]), "r"(a[2]), "r"(a[3]), "r"(b[0]), "r"(b[1]));
}

#define AS_LD 36            // As row stride (padded): frag bank = 4g+t, CF
#define BS_LD 136           // Bs row stride (padded): frag bank = 8t+g, CF
#define AS_SZ (128 * AS_LD) // 4608 u32
#define BS_SZ (32 * BS_LD)  // 4352 u32
#define GEMM_SMEM_BYTES ((2 * (AS_SZ + BS_SZ)) * 4)  // 71680 B

// Block 128x128, BK=32, 256 threads. 8 warps in 2(m) x 4(n); warp tile 64x32.
template <int ACT>  // 1: gelu epilogue; 0: +residual epilogue
__global__ void __launch_bounds__(256)
tgemm_kernel(const float* __restrict__ A,
             const float* __restrict__ B,
             const float* __restrict__ bias,
             const float* __restrict__ res,
             float* __restrict__ C,
             int M, int N, int K) {
    extern __shared__ unsigned sm[];
    // layout: As0 | As1 | Bs0 | Bs1
    unsigned* AsBase = sm;
    unsigned* BsBase = sm + 2 * AS_SZ;

    int tid = threadIdx.x;
    int brow = blockIdx.y, bcol = blockIdx.x;
    int w = tid >> 5, lane = tid & 31;
    int wm = w & 1, wn = w >> 1;          // 2 x 4 warps
    int g = lane >> 2, t = lane & 3;

    // global-load assignments (4 float4 each for A and B tiles)
    int ar = tid >> 3;            // 0..31 (+32*i)
    int ac = (tid & 7) * 4;       // k offset within tile
    int br = tid >> 5;            // 0..7  (+8*i)
    int bc = (tid & 31) * 4;      // n offset within tile

    const float* Ap = A + (size_t)(brow * 128 + ar) * K + ac;
    const float* Bp = B + (size_t)br * N + bcol * 128 + bc;

    float acc[4][4][4] = {};
    float4 pa[4], pb[4];

    // prologue: load tile 0, store into buffer 0
#pragma unroll
    for (int i = 0; i < 4; i++) {
        pa[i] = *(const float4*)(Ap + (size_t)(i * 32) * K);
        pb[i] = *(const float4*)(Bp + (size_t)(i * 8) * N);
    }
    {
        unsigned* As = AsBase;
        unsigned* Bs = BsBase;
#pragma unroll
        for (int i = 0; i < 4; i++) {
            unsigned* da = &As[(ar + 32 * i) * AS_LD + ac];
            da[0] = f2tf32(pa[i].x); da[1] = f2tf32(pa[i].y);
            da[2] = f2tf32(pa[i].z); da[3] = f2tf32(pa[i].w);
            unsigned* db = &Bs[(br + 8 * i) * BS_LD + bc];
            db[0] = f2tf32(pb[i].x); db[1] = f2tf32(pb[i].y);
            db[2] = f2tf32(pb[i].z); db[3] = f2tf32(pb[i].w);
        }
    }
    __syncthreads();

    int buf = 0;
    for (int k0 = 0; k0 < K; k0 += 32) {
        bool more = (k0 + 32 < K);
        if (more) {
#pragma unroll
            for (int i = 0; i < 4; i++) {
                pa[i] = *(const float4*)(Ap + (size_t)(i * 32) * K + k0 + 32);
                pb[i] = *(const float4*)(Bp + (size_t)(k0 + 32 + i * 8) * N);
            }
        }

        const unsigned* As = AsBase + buf * AS_SZ;
        const unsigned* Bs = BsBase + buf * BS_SZ;
#pragma unroll
        for (int ks = 0; ks < 4; ks++) {
            int kk = ks * 8 + t;
            unsigned af[4][4], bf[4][2];
#pragma unroll
            for (int mi = 0; mi < 4; mi++) {
                int r = wm * 64 + mi * 16 + g;
                af[mi][0] = As[r * AS_LD + kk];
                af[mi][1] = As[(r + 8) * AS_LD + kk];
                af[mi][2] = As[r * AS_LD + kk + 4];
                af[mi][3] = As[(r + 8) * AS_LD + kk + 4];
            }
#pragma unroll
            for (int ni = 0; ni < 4; ni++) {
                int n = wn * 32 + ni * 8 + g;
                bf[ni][0] = Bs[kk * BS_LD + n];
                bf[ni][1] = Bs[(kk + 4) * BS_LD + n];
            }
#pragma unroll
            for (int mi = 0; mi < 4; mi++)
#pragma unroll
                for (int ni = 0; ni < 4; ni++)
                    mma_tf32(acc[mi][ni], af[mi], bf[ni]);
        }

        if (more) {
            unsigned* Asn = AsBase + (buf ^ 1) * AS_SZ;
            unsigned* Bsn = BsBase + (buf ^ 1) * BS_SZ;
#pragma unroll
            for (int i = 0; i < 4; i++) {
                unsigned* da = &Asn[(ar + 32 * i) * AS_LD + ac];
                da[0] = f2tf32(pa[i].x); da[1] = f2tf32(pa[i].y);
                da[2] = f2tf32(pa[i].z); da[3] = f2tf32(pa[i].w);
                unsigned* db = &Bsn[(br + 8 * i) * BS_LD + bc];
                db[0] = f2tf32(pb[i].x); db[1] = f2tf32(pb[i].y);
                db[2] = f2tf32(pb[i].z); db[3] = f2tf32(pb[i].w);
            }
            __syncthreads();
            buf ^= 1;
        }
    }

    // epilogue: c0,c1 at (row0, col..col+1); c2,c3 at (row0+8, col..col+1)
#pragma unroll
    for (int mi = 0; mi < 4; mi++) {
        int row0 = brow * 128 + wm * 64 + mi * 16 + g;
#pragma unroll
        for (int ni = 0; ni < 4; ni++) {
            int col = bcol * 128 + wn * 32 + ni * 8 + 2 * t;
            float b0 = bias[col], b1 = bias[col + 1];
            float v0 = acc[mi][ni][0] + b0;
            float v1 = acc[mi][ni][1] + b1;
            float v2 = acc[mi][ni][2] + b0;
            float v3 = acc[mi][ni][3] + b1;
            if (ACT) {
                v0 = gelu_exact(v0); v1 = gelu_exact(v1);
                v2 = gelu_exact(v2); v3 = gelu_exact(v3);
            } else {
                const float* r0 = res + (size_t)row0 * N + col;
                const float* r1 = res + (size_t)(row0 + 8) * N + col;
                v0 += r0[0]; v1 += r0[1];
                v2 += r1[0]; v3 += r1[1];
            }
            float2* o0 = (float2*)(C + (size_t)row0 * N + col);
            float2* o1 = (float2*)(C + (size_t)(row0 + 8) * N + col);
            *o0 = make_float2(v0, v1);
            *o1 = make_float2(v2, v3);
        }
    }
}

// ---------------- launch -----------------------------------------------------
extern "C" void kernel_launch(void* const* d_in, const int* in_sizes, int n_in,
                              void* d_out, int out_size) {
    const float* x      = (const float*)d_in[0];
    const int*   adj    = (const int*)d_in[1];
    const float* stoich = (const float*)d_in[2];
    const float* ln1_g  = (const float*)d_in[3];
    const float* ln1_b  = (const float*)d_in[4];
    const float* ln2_g  = (const float*)d_in[5];
    const float* ln2_b  = (const float*)d_in[6];
    const float* W1     = (const float*)d_in[7];
    const float* b1     = (const float*)d_in[8];
    const float* W2     = (const float*)d_in[9];
    const float* b2     = (const float*)d_in[10];
    const float* gW     = (const float*)d_in[11];
    const float* gb     = (const float*)d_in[12];
    float* out = (float*)d_out;

    float *normed, *hbuf, *normed2, *mlp1;
    cudaGetSymbolAddress((void**)&normed,  g_normed);
    cudaGetSymbolAddress((void**)&hbuf,    g_h);
    cudaGetSymbolAddress((void**)&normed2, g_normed2);
    cudaGetSymbolAddress((void**)&mlp1,    g_mlp1);

    // raise dynamic smem limit for the double-buffered GEMM (idempotent)
    cudaFuncSetAttribute(tgemm_kernel<1>,
                         cudaFuncAttributeMaxDynamicSharedMemorySize,
                         GEMM_SMEM_BYTES);
    cudaFuncSetAttribute(tgemm_kernel<0>,
                         cudaFuncAttributeMaxDynamicSharedMemorySize,
                         GEMM_SMEM_BYTES);

    // 1. LN1
    ln_kernel<<<ROWS, 256>>>(x, ln1_g, ln1_b, normed);
    // 2. neighbor lists
    build_nbr_kernel<<<ROWS, 256>>>(adj);
    // 3. sparse attention + residual -> g_h
    attn_kernel<<<ROWS, 256>>>(x, stoich, gW, gb);
    // 4. LN2
    ln_kernel<<<ROWS, 256>>>(hbuf, ln2_g, ln2_b, normed2);
    // 5. mlp1 = gelu(normed2 @ W1 + b1)   [4096 x 4096] K=1024
    {
        dim3 grid(4 * Dd / 128, ROWS / 128);
        tgemm_kernel<1><<<grid, 256, GEMM_SMEM_BYTES>>>(normed2, W1, b1, nullptr, mlp1,
                                                        ROWS, 4 * Dd, Dd);
    }
    // 6. out = mlp1 @ W2 + b2 + g_h      [4096 x 1024] K=4096
    {
        dim3 grid(Dd / 128, ROWS / 128);
        tgemm_kernel<0><<<grid, 256, GEMM_SMEM_BYTES>>>(mlp1, W2, b2, hbuf, out,
                                                        ROWS, Dd, 4 * Dd);
    }
}